// round 4
// baseline (speedup 1.0000x reference)
#include <cuda_runtime.h>
#include <cuda_fp16.h>

#define L_FRAMES 16
#define C_CH     16
#define H_DIM    128
#define W_DIM    256
#define HW       (H_DIM * W_DIM)
#define DECAY_F  0.1f

// Channel-last fp16 scratch: [k][h][w][c], 16 MB
__device__ __half  g_imgT[L_FRAMES * HW * C_CH];
// Interleaved flow: [k][h][w] float2, 4 MB
__device__ float2 g_flow2[L_FRAMES * HW];

// ---------------------------------------------------------------------------
// Prep: transpose img [k][c][h][w] fp32 -> [k][h][w][c] fp16, pack flow.
// ---------------------------------------------------------------------------
__global__ void prep_kernel(const float* __restrict__ img,
                            const float* __restrict__ cum_flow) {
    const int kh = blockIdx.x;          // k*H + h
    const int w  = threadIdx.x;         // 0..255
    const int k  = kh >> 7;
    const int h  = kh & (H_DIM - 1);

    __half2 v[8];
#pragma unroll
    for (int c = 0; c < 8; c++) {
        float a = img[((k * C_CH + 2 * c + 0) * H_DIM + h) * W_DIM + w];
        float b = img[((k * C_CH + 2 * c + 1) * H_DIM + h) * W_DIM + w];
        v[c] = __floats2half2_rn(a, b);
    }
    uint4* dst = reinterpret_cast<uint4*>(&g_imgT[((size_t)kh * W_DIM + w) * C_CH]);
    dst[0] = *reinterpret_cast<const uint4*>(&v[0]);
    dst[1] = *reinterpret_cast<const uint4*>(&v[4]);

    const int p = h * W_DIM + w;
    const float fx = cum_flow[(k * 2 + 0) * HW + p];
    const float fy = cum_flow[(k * 2 + 1) * HW + p];
    g_flow2[k * HW + p] = make_float2(fx, fy);
}

// ---------------------------------------------------------------------------
// Warped accumulation. blockIdx.y = t, blockIdx.x covers 128 pixels.
// 2 lanes per pixel: ch = tid&1 selects channel half [ch*8, ch*8+8).
// Each lane loads all 4 bilinear taps (4x LDG.128, 16B each) and combines
// them fully in half2; fp32 accumulation across k.
// ---------------------------------------------------------------------------
__global__ void __launch_bounds__(256) sample_kernel(
    const float* __restrict__ mask,       // [t][k]
    const float* __restrict__ dist,       // [t][k]
    float* __restrict__ out)              // [t][c][h][w]
{
    const int t = blockIdx.y;

    __shared__ float ws[L_FRAMES];
    if (threadIdx.x < L_FRAMES) {
        int i = t * L_FRAMES + threadIdx.x;
        ws[threadIdx.x] = mask[i] * expf(-DECAY_F * dist[i]);
    }
    __syncthreads();

    const int tid = threadIdx.x;
    const int ch  = tid & 1;                        // channel half
    const int p   = blockIdx.x * 128 + (tid >> 1);  // pixel 0..32767
    const int h   = p >> 8;
    const int w   = p & (W_DIM - 1);

    const float2 ft = g_flow2[t * HW + p];

    // Hoisted affine coords: ix = Ax - 128*fkx ; iy = Ay - 64*fky
    const float base_x = (float)w * (2.0f / W_DIM) - 1.0f + (1.0f / W_DIM);
    const float base_y = (float)h * (2.0f / H_DIM) - 1.0f + (1.0f / H_DIM);
    const float Ax = (base_x + ft.x + 1.0f) * (W_DIM * 0.5f) - 0.5f;
    const float Ay = (base_y + ft.y + 1.0f) * (H_DIM * 0.5f) - 0.5f;

    float acc[8];
#pragma unroll
    for (int j = 0; j < 8; j++) acc[j] = 0.0f;

    // byte base for this lane's channel half (scratch is 16 MB: 32-bit offsets ok)
    const char* __restrict__ gbase = reinterpret_cast<const char*>(g_imgT) + ch * 16;
    const float2* __restrict__ flow = g_flow2 + p;

    for (int k = 0; k <= t; k++) {
        const float wk  = ws[k];
        const float2 fk = flow[k * HW];

        const float ix = fmaf(-(W_DIM * 0.5f), fk.x, Ax);
        const float iy = fmaf(-(H_DIM * 0.5f), fk.y, Ay);

        const int x0 = __float2int_rd(ix);
        const int y0 = __float2int_rd(iy);
        const float wx = ix - (float)x0;
        const float wy = iy - (float)y0;

        const int x0r = x0 & (W_DIM - 1);            // wrap
        const int x1r = (x0 + 1) & (W_DIM - 1);
        const int y0c = min(max(y0, 0), H_DIM - 1);  // clamp
        const int y1c = min(max(y0 + 1, 0), H_DIM - 1);

        // weights (wk folded in)
        const float w_1 = wk * wy;        // wk*wy
        const float w_0 = wk - w_1;       // wk*(1-wy)
        const float w01 = w_0 * wx;
        const float w00 = w_0 - w01;
        const float w11 = w_1 * wx;
        const float w10 = w_1 - w11;

        const __half2 h00 = __float2half2_rn(w00);
        const __half2 h01 = __float2half2_rn(w01);
        const __half2 h10 = __float2half2_rn(w10);
        const __half2 h11 = __float2half2_rn(w11);

        // 32-bit byte offsets: pixel index * 32 bytes
        const unsigned row0 = (unsigned)(k * HW + y0c * W_DIM) << 5;
        const unsigned row1 = (unsigned)(k * HW + y1c * W_DIM) << 5;
        const unsigned ox0  = (unsigned)x0r << 5;
        const unsigned ox1  = (unsigned)x1r << 5;

        const uint4 u00 = *reinterpret_cast<const uint4*>(gbase + (row0 + ox0));
        const uint4 u01 = *reinterpret_cast<const uint4*>(gbase + (row0 + ox1));
        const uint4 u10 = *reinterpret_cast<const uint4*>(gbase + (row1 + ox0));
        const uint4 u11 = *reinterpret_cast<const uint4*>(gbase + (row1 + ox1));

        const __half2* a = reinterpret_cast<const __half2*>(&u00);
        const __half2* b = reinterpret_cast<const __half2*>(&u01);
        const __half2* c = reinterpret_cast<const __half2*>(&u10);
        const __half2* d = reinterpret_cast<const __half2*>(&u11);
#pragma unroll
        for (int j = 0; j < 4; j++) {
            __half2 s = __hmul2(a[j], h00);
            s = __hfma2(b[j], h01, s);
            s = __hfma2(c[j], h10, s);
            s = __hfma2(d[j], h11, s);
            const float2 f = __half22float2(s);
            acc[2 * j + 0] += f.x;
            acc[2 * j + 1] += f.y;
        }
    }

    const int cbase = (t * C_CH + ch * 8) * HW + p;
#pragma unroll
    for (int j = 0; j < 8; j++)
        out[cbase + j * HW] = acc[j];
}

extern "C" void kernel_launch(void* const* d_in, const int* in_sizes, int n_in,
                              void* d_out, int out_size) {
    const float* img      = (const float*)d_in[0];  // (1,16,16,128,256)
    const float* cum_flow = (const float*)d_in[1];  // (1,16,2,128,256)
    const float* mask     = (const float*)d_in[2];  // (16,16)
    const float* dist     = (const float*)d_in[3];  // (16,16)
    float* out            = (float*)d_out;          // (1,16,16,128,256)

    prep_kernel<<<L_FRAMES * H_DIM, W_DIM>>>(img, cum_flow);

    dim3 grid(HW / 128, L_FRAMES);  // 256 x 16 blocks
    sample_kernel<<<grid, 256>>>(mask, dist, out);
}

// round 5
// speedup vs baseline: 1.1205x; 1.1205x over previous
#include <cuda_runtime.h>
#include <cuda_fp16.h>

#define L_FRAMES 16
#define C_CH     16
#define H_DIM    128
#define W_DIM    256
#define HW       (H_DIM * W_DIM)
#define DECAY_F  0.1f

// Channel-last fp16 scratch: [k][h][w][c], 16 MB
__device__ __half  g_imgT[L_FRAMES * HW * C_CH];
// Interleaved flow: [k][h][w] float2, 4 MB
__device__ float2 g_flow2[L_FRAMES * HW];

// ---------------------------------------------------------------------------
// Prep: transpose img [k][c][h][w] fp32 -> [k][h][w][c] fp16, pack flow.
// ---------------------------------------------------------------------------
__global__ void prep_kernel(const float* __restrict__ img,
                            const float* __restrict__ cum_flow) {
    const int kh = blockIdx.x;          // k*H + h
    const int w  = threadIdx.x;         // 0..255
    const int k  = kh >> 7;
    const int h  = kh & (H_DIM - 1);

    __half2 v[8];
#pragma unroll
    for (int c = 0; c < 8; c++) {
        float a = img[((k * C_CH + 2 * c + 0) * H_DIM + h) * W_DIM + w];
        float b = img[((k * C_CH + 2 * c + 1) * H_DIM + h) * W_DIM + w];
        v[c] = __floats2half2_rn(a, b);
    }
    uint4* dst = reinterpret_cast<uint4*>(&g_imgT[((size_t)kh * W_DIM + w) * C_CH]);
    dst[0] = *reinterpret_cast<const uint4*>(&v[0]);
    dst[1] = *reinterpret_cast<const uint4*>(&v[4]);

    const int p = h * W_DIM + w;
    const float fx = cum_flow[(k * 2 + 0) * HW + p];
    const float fy = cum_flow[(k * 2 + 1) * HW + p];
    g_flow2[k * HW + p] = make_float2(fx, fy);
}

// ---------------------------------------------------------------------------
// Warped accumulation. blockIdx.y = t, blockIdx.x covers 64 pixels.
// 4 lanes per pixel: ch = sub&1 (16B channel half), xh = sub>>1 (32B x tap),
// so the 4 lanes of a pixel cover 64B contiguous inside each LDG -> minimal
// L1 wavefronts. 32-bit byte addressing, pointer-carried k stride.
// ---------------------------------------------------------------------------
__global__ void __launch_bounds__(256) sample_kernel(
    const float* __restrict__ mask,       // [t][k]
    const float* __restrict__ dist,       // [t][k]
    float* __restrict__ out)              // [t][c][h][w]
{
    const int t = blockIdx.y;

    __shared__ float ws[L_FRAMES];
    if (threadIdx.x < L_FRAMES) {
        int i = t * L_FRAMES + threadIdx.x;
        ws[threadIdx.x] = mask[i] * expf(-DECAY_F * dist[i]);
    }
    __syncthreads();

    const int tid = threadIdx.x;
    const int sub = tid & 3;
    const int ch  = sub & 1;        // channel half: channels [ch*8, ch*8+8)
    const int xh  = sub >> 1;       // x tap: 0 -> x0, 1 -> x0+1
    const int p   = blockIdx.x * 64 + (tid >> 2);   // pixel 0..32767
    const int h   = p >> 8;
    const int w   = p & (W_DIM - 1);

    const float2 ft = g_flow2[t * HW + p];

    // Hoisted affine coords: ix = Ax - 128*fkx ; iy = Ay - 64*fky
    const float base_x = (float)w * (2.0f / W_DIM) - 1.0f + (1.0f / W_DIM);
    const float base_y = (float)h * (2.0f / H_DIM) - 1.0f + (1.0f / H_DIM);
    const float Ax = (base_x + ft.x + 1.0f) * (W_DIM * 0.5f) - 0.5f;
    const float Ay = (base_y + ft.y + 1.0f) * (H_DIM * 0.5f) - 0.5f;

    // xw = xh ? wx : 1-wx  ->  xw = fma(sx, wx, cx)
    const float sx = xh ? 1.0f : -1.0f;
    const float cx = xh ? 0.0f : 1.0f;

    float acc[8];
#pragma unroll
    for (int j = 0; j < 8; j++) acc[j] = 0.0f;

    // per-lane byte base: channel-half offset (16B); k advances by HW*32 bytes
    const char* __restrict__ kbase = reinterpret_cast<const char*>(g_imgT) + ch * 16;
    const float2* __restrict__ flow = g_flow2 + p;

    for (int k = 0; k <= t; k++) {
        const float wk  = ws[k];
        const float2 fk = *flow;
        flow += HW;

        const float ix = fmaf(-(W_DIM * 0.5f), fk.x, Ax);
        const float iy = fmaf(-(H_DIM * 0.5f), fk.y, Ay);

        const int x0 = __float2int_rd(ix);
        const int y0 = __float2int_rd(iy);
        const float wx = ix - (float)x0;
        const float wy = iy - (float)y0;

        const int x   = (x0 + xh) & (W_DIM - 1);      // wrap
        const int y0c = min(max(y0, 0), H_DIM - 1);   // clamp
        const int y1c = min(max(y0 + 1, 0), H_DIM - 1);

        const float xw = fmaf(sx, wx, cx);
        const float tw = wk * xw;
        const float w1 = tw * wy;
        const float w0 = tw - w1;

        const __half2 w0h = __float2half2_rn(w0);
        const __half2 w1h = __float2half2_rn(w1);

        // 32-bit byte offsets within one frame (4 MB)
        const unsigned ox   = (unsigned)x << 5;            // x * 32B
        const unsigned off0 = ((unsigned)y0c << 13) + ox;   // y * 256 * 32B
        const unsigned off1 = ((unsigned)y1c << 13) + ox;

        const uint4 u0 = *reinterpret_cast<const uint4*>(kbase + off0);
        const uint4 u1 = *reinterpret_cast<const uint4*>(kbase + off1);
        kbase += HW * 32;

        const __half2* h0 = reinterpret_cast<const __half2*>(&u0);
        const __half2* h1 = reinterpret_cast<const __half2*>(&u1);
#pragma unroll
        for (int j = 0; j < 4; j++) {
            __half2 s = __hmul2(h0[j], w0h);
            s = __hfma2(h1[j], w1h, s);
            const float2 f = __half22float2(s);
            acc[2 * j + 0] += f.x;
            acc[2 * j + 1] += f.y;
        }
    }

    // merge x-halves: partner lane differs in bit 1 of tid
#pragma unroll
    for (int j = 0; j < 8; j++)
        acc[j] += __shfl_xor_sync(0xffffffffu, acc[j], 2);

    // each lane writes 4 channels: [ch*8 + xh*4, +4)
    const int cbase = (t * C_CH + ch * 8 + xh * 4) * HW + p;
#pragma unroll
    for (int j = 0; j < 4; j++)
        out[cbase + j * HW] = acc[xh * 4 + j];
}

extern "C" void kernel_launch(void* const* d_in, const int* in_sizes, int n_in,
                              void* d_out, int out_size) {
    const float* img      = (const float*)d_in[0];  // (1,16,16,128,256)
    const float* cum_flow = (const float*)d_in[1];  // (1,16,2,128,256)
    const float* mask     = (const float*)d_in[2];  // (16,16)
    const float* dist     = (const float*)d_in[3];  // (16,16)
    float* out            = (float*)d_out;          // (1,16,16,128,256)

    prep_kernel<<<L_FRAMES * H_DIM, W_DIM>>>(img, cum_flow);

    dim3 grid(HW / 64, L_FRAMES);   // 512 x 16 blocks
    sample_kernel<<<grid, 256>>>(mask, dist, out);
}